// round 5
// baseline (speedup 1.0000x reference)
#include <cuda_runtime.h>

// ScorePredictor: 3x DistMult edge scoring.
// score[e] = clip( sum_d head[src[e],d] * rel[d] * tail[dst[e],d], 0, 1 )
//
// Pipeline per call (all graph-capturable, allocation-free):
//  1. zero histograms
//  2. histogram of the "grouping key" per phase (ddi:src, dpi:dst, ppi:src)
//  3. exclusive scan (1 block per phase)
//  4. scatter -> sorted edge permutation per phase
//  5. 3x score kernels: each warp handles 8 consecutive SORTED edges, so the
//     shared head row is L1/L2 hot; rel vector preloaded into registers once
//     per warp and reused across the 8 edges (cuts rel L1 wavefronts 8x).

#define D_DIM 2048
#define WARPS_PER_BLOCK 8
#define THREADS_PER_BLOCK (WARPS_PER_BLOCK * 32)
#define EDGES_PER_WARP 8
#define EDGES_PER_BLOCK (WARPS_PER_BLOCK * EDGES_PER_WARP)

#define MAX_BINS 32768
#define MAX_E    131072

__device__ int g_hist[3][MAX_BINS];
__device__ int g_perm[3][MAX_E];

struct f8 { float v[8]; };

__device__ __forceinline__ f8 ldg_f8(const float* p) {
    unsigned r0, r1, r2, r3, r4, r5, r6, r7;
    asm volatile(
        "ld.global.nc.v8.b32 {%0,%1,%2,%3,%4,%5,%6,%7}, [%8];"
        : "=r"(r0), "=r"(r1), "=r"(r2), "=r"(r3),
          "=r"(r4), "=r"(r5), "=r"(r6), "=r"(r7)
        : "l"(p));
    f8 o;
    o.v[0] = __uint_as_float(r0); o.v[1] = __uint_as_float(r1);
    o.v[2] = __uint_as_float(r2); o.v[3] = __uint_as_float(r3);
    o.v[4] = __uint_as_float(r4); o.v[5] = __uint_as_float(r5);
    o.v[6] = __uint_as_float(r6); o.v[7] = __uint_as_float(r7);
    return o;
}

// ---------------- sort: zero / hist / scan / scatter ----------------

__global__ void zero_hist_kernel() {
    int i = blockIdx.x * blockDim.x + threadIdx.x;
    if (i < 3 * MAX_BINS) ((int*)g_hist)[i] = 0;
}

__global__ void hist_kernel(const int* __restrict__ k0,   // ddi_src
                            const int* __restrict__ k1,   // dpi_dst
                            const int* __restrict__ k2,   // ppi_src
                            int E) {
    int i = blockIdx.x * blockDim.x + threadIdx.x;
    if (i >= 3 * E) return;
    int p = i / E, e = i - p * E;
    int key = (p == 0) ? __ldg(k0 + e) : (p == 1) ? __ldg(k1 + e) : __ldg(k2 + e);
    atomicAdd(&g_hist[p][key], 1);
}

__global__ void scan_kernel(int nbins0, int nbins12) {
    const int p = blockIdx.x;           // one block per phase
    const int nbins = (p == 0) ? nbins0 : nbins12;
    int* h = g_hist[p];
    const int T = 1024;
    const int t = threadIdx.x;
    __shared__ int buf[2][1024];

    int chunk = (nbins + T - 1) / T;
    int start = t * chunk;
    int end   = min(start + chunk, nbins);

    int s = 0;
    for (int i = start; i < end; ++i) s += h[i];
    buf[0][t] = s;
    __syncthreads();

    // Hillis-Steele inclusive scan, ping-pong buffers
    int src = 0;
    for (int off = 1; off < T; off <<= 1) {
        int v = buf[src][t];
        if (t >= off) v += buf[src][t - off];
        buf[src ^ 1][t] = v;
        src ^= 1;
        __syncthreads();
    }

    int base = (t == 0) ? 0 : buf[src][t - 1];
    int run = base;
    for (int i = start; i < end; ++i) {
        int v = h[i];
        h[i] = run;
        run += v;
    }
}

__global__ void scatter_kernel(const int* __restrict__ k0,
                               const int* __restrict__ k1,
                               const int* __restrict__ k2,
                               int E) {
    int i = blockIdx.x * blockDim.x + threadIdx.x;
    if (i >= 3 * E) return;
    int p = i / E, e = i - p * E;
    int key = (p == 0) ? __ldg(k0 + e) : (p == 1) ? __ldg(k1 + e) : __ldg(k2 + e);
    int pos = atomicAdd(&g_hist[p][key], 1);
    g_perm[p][pos] = e;
}

// ---------------- score ----------------

// PHASE selects which perm array to use (compile-time for clean addressing).
template <int PHASE>
__global__ __launch_bounds__(THREADS_PER_BLOCK)
void edge_score_sorted(
    const float* __restrict__ x_head,
    const float* __restrict__ x_tail,
    const float* __restrict__ rel,
    const int*   __restrict__ src,
    const int*   __restrict__ dst,
    float*       __restrict__ out,
    int E)
{
    const int warp = threadIdx.x >> 5;
    const int lane = threadIdx.x & 31;
    const int warp_global = blockIdx.x * WARPS_PER_BLOCK + warp;
    const int base = warp_global * EDGES_PER_WARP;
    if (base >= E) return;

    // Preload this lane's 64 rel values (8 chunks x 8 floats) once per warp.
    float4 ra[8], rb[8];
    #pragma unroll
    for (int k = 0; k < 8; ++k) {
        const int idx = (k * 32 + lane) * 8;
        ra[k] = __ldg(reinterpret_cast<const float4*>(rel + idx));
        rb[k] = __ldg(reinterpret_cast<const float4*>(rel + idx + 4));
    }

    #pragma unroll 1
    for (int e = 0; e < EDGES_PER_WARP; ++e) {
        const int pos = base + e;
        if (pos >= E) break;
        const int edge = __ldg(&g_perm[PHASE][pos]);
        const float* head = x_head + (size_t)__ldg(src + edge) * D_DIM;
        const float* tail = x_tail + (size_t)__ldg(dst + edge) * D_DIM;

        float acc = 0.0f;
        #pragma unroll
        for (int k = 0; k < 8; ++k) {
            const int idx = (k * 32 + lane) * 8;
            f8 h = ldg_f8(head + idx);
            f8 t = ldg_f8(tail + idx);
            acc = fmaf(h.v[0] * ra[k].x, t.v[0], acc);
            acc = fmaf(h.v[1] * ra[k].y, t.v[1], acc);
            acc = fmaf(h.v[2] * ra[k].z, t.v[2], acc);
            acc = fmaf(h.v[3] * ra[k].w, t.v[3], acc);
            acc = fmaf(h.v[4] * rb[k].x, t.v[4], acc);
            acc = fmaf(h.v[5] * rb[k].y, t.v[5], acc);
            acc = fmaf(h.v[6] * rb[k].z, t.v[6], acc);
            acc = fmaf(h.v[7] * rb[k].w, t.v[7], acc);
        }

        #pragma unroll
        for (int off = 16; off > 0; off >>= 1)
            acc += __shfl_xor_sync(0xffffffffu, acc, off);

        if (lane == 0)
            out[edge] = fminf(fmaxf(acc, 0.0f), 1.0f);
    }
}

// ---------------- launch ----------------

extern "C" void kernel_launch(void* const* d_in, const int* in_sizes, int n_in,
                              void* d_out, int out_size)
{
    const float* x_drug  = (const float*)d_in[0];
    const float* x_prot  = (const float*)d_in[1];
    const float* rel_ddi = (const float*)d_in[2];
    const float* rel_dpi = (const float*)d_in[3];
    const int*   ddi_src = (const int*)d_in[4];
    const int*   ddi_dst = (const int*)d_in[5];
    const int*   dpi_src = (const int*)d_in[6];
    const int*   dpi_dst = (const int*)d_in[7];
    const int*   ppi_src = (const int*)d_in[8];
    const int*   ppi_dst = (const int*)d_in[9];
    float* out = (float*)d_out;

    const int E      = in_sizes[4];
    const int N_DRUG = in_sizes[0] / D_DIM;
    const int N_PROT = in_sizes[1] / D_DIM;

    // --- sort each phase by its grouping key ---
    zero_hist_kernel<<<(3 * MAX_BINS + 255) / 256, 256>>>();
    hist_kernel<<<(3 * E + 255) / 256, 256>>>(ddi_src, dpi_dst, ppi_src, E);
    scan_kernel<<<3, 1024>>>(N_DRUG, N_PROT);
    scatter_kernel<<<(3 * E + 255) / 256, 256>>>(ddi_src, dpi_dst, ppi_src, E);

    const int blocks = (E + EDGES_PER_BLOCK - 1) / EDGES_PER_BLOCK;

    // Phase 0: ddi — sorted by src (drug). head rows L1-hot.
    edge_score_sorted<0><<<blocks, THREADS_PER_BLOCK>>>(
        x_drug, x_drug, rel_ddi, ddi_src, ddi_dst, out, E);

    // Phase 1: dpi — sorted by dst (protein). tail rows (the big table) L1-hot;
    // drug heads random but the 80MB drug table fits L2.
    edge_score_sorted<1><<<blocks, THREADS_PER_BLOCK>>>(
        x_drug, x_prot, rel_dpi, dpi_src, dpi_dst, out + E, E);

    // Phase 2: ppi — sorted by src (protein). head rows L1-hot.
    edge_score_sorted<2><<<blocks, THREADS_PER_BLOCK>>>(
        x_prot, x_prot, rel_dpi, ppi_src, ppi_dst, out + 2 * E, E);
}

// round 6
// speedup vs baseline: 1.7367x; 1.7367x over previous
#include <cuda_runtime.h>

// ScorePredictor: 3x DistMult edge scoring.
// score[e] = clip( sum_d head[src[e],d] * rel[d] * tail[dst[e],d], 0, 1 )
//
// Pipeline (graph-capturable, allocation-free):
//  1. counting sort of each edge list by one endpoint (hist/scan/scatter)
//  2. score kernels: warp handles 8 consecutive SORTED edges with k-chunk as
//     the OUTER loop: rel chunk loaded once per k (traffic /8), head chunk
//     reloaded only when the sorted key changes (traffic /run-length),
//     8 independent tail loads per k-iter keep MLP high.

#define D_DIM 2048
#define WARPS_PER_BLOCK 8
#define THREADS_PER_BLOCK (WARPS_PER_BLOCK * 32)
#define EDGES_PER_WARP 8
#define EDGES_PER_BLOCK (WARPS_PER_BLOCK * EDGES_PER_WARP)

#define MAX_BINS 32768
#define MAX_E    131072

__device__ int g_hist[3][MAX_BINS];
__device__ int g_perm[3][MAX_E];

struct f8 { float v[8]; };

__device__ __forceinline__ f8 ldg_f8(const float* p) {
    unsigned r0, r1, r2, r3, r4, r5, r6, r7;
    asm volatile(
        "ld.global.nc.v8.b32 {%0,%1,%2,%3,%4,%5,%6,%7}, [%8];"
        : "=r"(r0), "=r"(r1), "=r"(r2), "=r"(r3),
          "=r"(r4), "=r"(r5), "=r"(r6), "=r"(r7)
        : "l"(p));
    f8 o;
    o.v[0] = __uint_as_float(r0); o.v[1] = __uint_as_float(r1);
    o.v[2] = __uint_as_float(r2); o.v[3] = __uint_as_float(r3);
    o.v[4] = __uint_as_float(r4); o.v[5] = __uint_as_float(r5);
    o.v[6] = __uint_as_float(r6); o.v[7] = __uint_as_float(r7);
    return o;
}

// ---------------- sort: zero / hist / scan / scatter ----------------

__global__ void zero_hist_kernel() {
    int i = blockIdx.x * blockDim.x + threadIdx.x;
    if (i < 3 * MAX_BINS) ((int*)g_hist)[i] = 0;
}

__global__ void hist_kernel(const int* __restrict__ k0,   // ddi_src
                            const int* __restrict__ k1,   // dpi_dst
                            const int* __restrict__ k2,   // ppi_src
                            int E) {
    int i = blockIdx.x * blockDim.x + threadIdx.x;
    if (i >= 3 * E) return;
    int p = i / E, e = i - p * E;
    int key = (p == 0) ? __ldg(k0 + e) : (p == 1) ? __ldg(k1 + e) : __ldg(k2 + e);
    atomicAdd(&g_hist[p][key], 1);
}

__global__ void scan_kernel(int nbins0, int nbins12) {
    const int p = blockIdx.x;           // one block per phase
    const int nbins = (p == 0) ? nbins0 : nbins12;
    int* h = g_hist[p];
    const int T = 1024;
    const int t = threadIdx.x;
    __shared__ int buf[2][1024];

    int chunk = (nbins + T - 1) / T;
    int start = t * chunk;
    int end   = min(start + chunk, nbins);

    int s = 0;
    for (int i = start; i < end; ++i) s += h[i];
    buf[0][t] = s;
    __syncthreads();

    int src = 0;
    for (int off = 1; off < T; off <<= 1) {
        int v = buf[src][t];
        if (t >= off) v += buf[src][t - off];
        buf[src ^ 1][t] = v;
        src ^= 1;
        __syncthreads();
    }

    int base = (t == 0) ? 0 : buf[src][t - 1];
    int run = base;
    for (int i = start; i < end; ++i) {
        int v = h[i];
        h[i] = run;
        run += v;
    }
}

__global__ void scatter_kernel(const int* __restrict__ k0,
                               const int* __restrict__ k1,
                               const int* __restrict__ k2,
                               int E) {
    int i = blockIdx.x * blockDim.x + threadIdx.x;
    if (i >= 3 * E) return;
    int p = i / E, e = i - p * E;
    int key = (p == 0) ? __ldg(k0 + e) : (p == 1) ? __ldg(k1 + e) : __ldg(k2 + e);
    int pos = atomicAdd(&g_hist[p][key], 1);
    g_perm[p][pos] = e;
}

// ---------------- score ----------------

template <int PHASE>
__global__ __launch_bounds__(THREADS_PER_BLOCK, 2)
void edge_score_grouped(
    const float* __restrict__ x_sorted,   // table indexed by the sorted key
    const float* __restrict__ x_rand,     // table indexed by the other endpoint
    const float* __restrict__ rel,
    const int*   __restrict__ key,        // sorted-side endpoint per edge
    const int*   __restrict__ other,      // random-side endpoint per edge
    float*       __restrict__ out,
    int E)
{
    const int warp = threadIdx.x >> 5;
    const int lane = threadIdx.x & 31;
    const int base = (blockIdx.x * WARPS_PER_BLOCK + warp) * EDGES_PER_WARP;
    if (base >= E) return;

    // Lanes 0..7 fetch edge metadata; broadcast to the warp via shuffles.
    int pos = base + lane;
    if (pos >= E) pos = E - 1;              // duplicate last edge (same output)
    int my_edge = 0, my_s = 0, my_d = 0;
    if (lane < EDGES_PER_WARP) {
        my_edge = __ldg(&g_perm[PHASE][pos]);
        my_s    = __ldg(key + my_edge);
        my_d    = __ldg(other + my_edge);
    }

    int s[EDGES_PER_WARP], dI[EDGES_PER_WARP];
    #pragma unroll
    for (int e = 0; e < EDGES_PER_WARP; ++e) {
        s[e]  = __shfl_sync(0xffffffffu, my_s, e);
        dI[e] = __shfl_sync(0xffffffffu, my_d, e);
    }

    float acc[EDGES_PER_WARP];
    #pragma unroll
    for (int e = 0; e < EDGES_PER_WARP; ++e) acc[e] = 0.0f;

    // Outer loop over 8 dim-chunks; inner loop over the warp's 8 edges.
    #pragma unroll
    for (int k = 0; k < D_DIM / (32 * 8); ++k) {
        const int idx = (k * 32 + lane) * 8;
        const float4 r0 = __ldg(reinterpret_cast<const float4*>(rel + idx));
        const float4 r1 = __ldg(reinterpret_cast<const float4*>(rel + idx + 4));

        f8 hr;   // head chunk pre-multiplied by rel; reloaded on key change only
        #pragma unroll
        for (int e = 0; e < EDGES_PER_WARP; ++e) {
            if (e == 0 || s[e] != s[e - 1]) {   // warp-uniform branch
                f8 h = ldg_f8(x_sorted + (size_t)s[e] * D_DIM + idx);
                hr.v[0] = h.v[0] * r0.x;  hr.v[1] = h.v[1] * r0.y;
                hr.v[2] = h.v[2] * r0.z;  hr.v[3] = h.v[3] * r0.w;
                hr.v[4] = h.v[4] * r1.x;  hr.v[5] = h.v[5] * r1.y;
                hr.v[6] = h.v[6] * r1.z;  hr.v[7] = h.v[7] * r1.w;
            }
            f8 t = ldg_f8(x_rand + (size_t)dI[e] * D_DIM + idx);
            acc[e] = fmaf(hr.v[0], t.v[0], acc[e]);
            acc[e] = fmaf(hr.v[1], t.v[1], acc[e]);
            acc[e] = fmaf(hr.v[2], t.v[2], acc[e]);
            acc[e] = fmaf(hr.v[3], t.v[3], acc[e]);
            acc[e] = fmaf(hr.v[4], t.v[4], acc[e]);
            acc[e] = fmaf(hr.v[5], t.v[5], acc[e]);
            acc[e] = fmaf(hr.v[6], t.v[6], acc[e]);
            acc[e] = fmaf(hr.v[7], t.v[7], acc[e]);
        }
    }

    // Reduce and write each edge's score.
    #pragma unroll
    for (int e = 0; e < EDGES_PER_WARP; ++e) {
        float a = acc[e];
        #pragma unroll
        for (int off = 16; off > 0; off >>= 1)
            a += __shfl_xor_sync(0xffffffffu, a, off);
        const int edge_e = __shfl_sync(0xffffffffu, my_edge, e);
        if (lane == 0)
            out[edge_e] = fminf(fmaxf(a, 0.0f), 1.0f);
    }
}

// ---------------- launch ----------------

extern "C" void kernel_launch(void* const* d_in, const int* in_sizes, int n_in,
                              void* d_out, int out_size)
{
    const float* x_drug  = (const float*)d_in[0];
    const float* x_prot  = (const float*)d_in[1];
    const float* rel_ddi = (const float*)d_in[2];
    const float* rel_dpi = (const float*)d_in[3];
    const int*   ddi_src = (const int*)d_in[4];
    const int*   ddi_dst = (const int*)d_in[5];
    const int*   dpi_src = (const int*)d_in[6];
    const int*   dpi_dst = (const int*)d_in[7];
    const int*   ppi_src = (const int*)d_in[8];
    const int*   ppi_dst = (const int*)d_in[9];
    float* out = (float*)d_out;

    const int E      = in_sizes[4];
    const int N_DRUG = in_sizes[0] / D_DIM;
    const int N_PROT = in_sizes[1] / D_DIM;

    // Sort each edge list by its grouping endpoint (ddi:src, dpi:dst, ppi:src).
    zero_hist_kernel<<<(3 * MAX_BINS + 255) / 256, 256>>>();
    hist_kernel<<<(3 * E + 255) / 256, 256>>>(ddi_src, dpi_dst, ppi_src, E);
    scan_kernel<<<3, 1024>>>(N_DRUG, N_PROT);
    scatter_kernel<<<(3 * E + 255) / 256, 256>>>(ddi_src, dpi_dst, ppi_src, E);

    const int blocks = (E + EDGES_PER_BLOCK - 1) / EDGES_PER_BLOCK;

    // Phase 0: ddi — sorted by src (drug); heads register/L1-hot.
    edge_score_grouped<0><<<blocks, THREADS_PER_BLOCK>>>(
        x_drug, x_drug, rel_ddi, ddi_src, ddi_dst, out, E);

    // Phase 1: dpi — sorted by dst (protein); protein side is the "head".
    edge_score_grouped<1><<<blocks, THREADS_PER_BLOCK>>>(
        x_prot, x_drug, rel_dpi, dpi_dst, dpi_src, out + E, E);

    // Phase 2: ppi — sorted by src (protein).
    edge_score_grouped<2><<<blocks, THREADS_PER_BLOCK>>>(
        x_prot, x_prot, rel_dpi, ppi_src, ppi_dst, out + 2 * E, E);
}

// round 7
// speedup vs baseline: 1.9280x; 1.1101x over previous
#include <cuda_runtime.h>

// ScorePredictor: 3x DistMult edge scoring.
// score[e] = clip( sum_d head[src[e],d] * rel[d] * tail[dst[e],d], 0, 1 )
//
// Pipeline (graph-capturable, allocation-free):
//  1. counting sort of each edge list by one endpoint (hist/scan/scatter)
//  2. ONE fused score kernel; each warp handles 8 consecutive SORTED edges,
//     k-chunk outer loop. Per k-iter: rel chunk loaded once, head chunk
//     reloaded only on key change, and ALL 8 tail loads issued as a batch
//     (plain __ldg float4, schedulable -> MLP=8/warp) before the FMAs.

#define D_DIM 2048
#define WARPS_PER_BLOCK 8
#define THREADS_PER_BLOCK (WARPS_PER_BLOCK * 32)
#define EDGES_PER_WARP 8
#define EDGES_PER_BLOCK (WARPS_PER_BLOCK * EDGES_PER_WARP)

#define MAX_BINS 32768
#define MAX_E    131072

__device__ int g_hist[3][MAX_BINS];
__device__ int g_perm[3][MAX_E];

// ---------------- sort: zero / hist / scan / scatter ----------------

__global__ void zero_hist_kernel() {
    int i = blockIdx.x * blockDim.x + threadIdx.x;
    if (i < 3 * MAX_BINS) ((int*)g_hist)[i] = 0;
}

__global__ void hist_kernel(const int* __restrict__ k0,   // ddi_src
                            const int* __restrict__ k1,   // dpi_dst
                            const int* __restrict__ k2,   // ppi_src
                            int E) {
    int i = blockIdx.x * blockDim.x + threadIdx.x;
    if (i >= 3 * E) return;
    int p = i / E, e = i - p * E;
    int key = (p == 0) ? __ldg(k0 + e) : (p == 1) ? __ldg(k1 + e) : __ldg(k2 + e);
    atomicAdd(&g_hist[p][key], 1);
}

__global__ void scan_kernel(int nbins0, int nbins12) {
    const int p = blockIdx.x;           // one block per phase
    const int nbins = (p == 0) ? nbins0 : nbins12;
    int* h = g_hist[p];
    const int T = 1024;
    const int t = threadIdx.x;
    __shared__ int buf[2][1024];

    int chunk = (nbins + T - 1) / T;
    int start = t * chunk;
    int end   = min(start + chunk, nbins);

    int s = 0;
    for (int i = start; i < end; ++i) s += h[i];
    buf[0][t] = s;
    __syncthreads();

    int src = 0;
    for (int off = 1; off < T; off <<= 1) {
        int v = buf[src][t];
        if (t >= off) v += buf[src][t - off];
        buf[src ^ 1][t] = v;
        src ^= 1;
        __syncthreads();
    }

    int base = (t == 0) ? 0 : buf[src][t - 1];
    int run = base;
    for (int i = start; i < end; ++i) {
        int v = h[i];
        h[i] = run;
        run += v;
    }
}

__global__ void scatter_kernel(const int* __restrict__ k0,
                               const int* __restrict__ k1,
                               const int* __restrict__ k2,
                               int E) {
    int i = blockIdx.x * blockDim.x + threadIdx.x;
    if (i >= 3 * E) return;
    int p = i / E, e = i - p * E;
    int key = (p == 0) ? __ldg(k0 + e) : (p == 1) ? __ldg(k1 + e) : __ldg(k2 + e);
    int pos = atomicAdd(&g_hist[p][key], 1);
    g_perm[p][pos] = e;
}

// ---------------- fused score ----------------

__global__ __launch_bounds__(THREADS_PER_BLOCK, 3)
void edge_score_fused(
    const float* __restrict__ x_drug,
    const float* __restrict__ x_prot,
    const float* __restrict__ rel_ddi,
    const float* __restrict__ rel_dpi,
    const int*   __restrict__ ddi_src, const int* __restrict__ ddi_dst,
    const int*   __restrict__ dpi_src, const int* __restrict__ dpi_dst,
    const int*   __restrict__ ppi_src, const int* __restrict__ ppi_dst,
    float*       __restrict__ out,
    int E, int blocks_per_phase)
{
    const int phase = blockIdx.x / blocks_per_phase;
    const int blk   = blockIdx.x - phase * blocks_per_phase;

    // Per-phase table binding. "sorted" side = the endpoint we counting-sorted
    // by (ddi:src drug, dpi:dst protein, ppi:src protein); other side random.
    const float* xs;   const float* xr;   const float* rel;
    const int* key;    const int* other;  const int* perm;
    float* o;
    if (phase == 0) {
        xs = x_drug; xr = x_drug; rel = rel_ddi;
        key = ddi_src; other = ddi_dst; perm = g_perm[0]; o = out;
    } else if (phase == 1) {
        xs = x_prot; xr = x_drug; rel = rel_dpi;
        key = dpi_dst; other = dpi_src; perm = g_perm[1]; o = out + E;
    } else {
        xs = x_prot; xr = x_prot; rel = rel_dpi;
        key = ppi_src; other = ppi_dst; perm = g_perm[2]; o = out + 2 * E;
    }

    const int warp = threadIdx.x >> 5;
    const int lane = threadIdx.x & 31;
    const int base = (blk * WARPS_PER_BLOCK + warp) * EDGES_PER_WARP;
    if (base >= E) return;

    // Lanes 0..7 fetch edge metadata; broadcast via shuffles.
    int pos = base + lane;
    if (pos >= E) pos = E - 1;              // duplicate last edge (same output)
    int my_edge = 0, my_s = 0, my_d = 0;
    if (lane < EDGES_PER_WARP) {
        my_edge = __ldg(perm + pos);
        my_s    = __ldg(key + my_edge);
        my_d    = __ldg(other + my_edge);
    }

    int s[EDGES_PER_WARP], dI[EDGES_PER_WARP];
    #pragma unroll
    for (int e = 0; e < EDGES_PER_WARP; ++e) {
        s[e]  = __shfl_sync(0xffffffffu, my_s, e);
        dI[e] = __shfl_sync(0xffffffffu, my_d, e);
    }

    float acc[EDGES_PER_WARP];
    #pragma unroll
    for (int e = 0; e < EDGES_PER_WARP; ++e) acc[e] = 0.0f;

    // 16 k-chunks of float4 per lane. Batch all 8 independent tail loads
    // before the FMA block so ptxas issues them back-to-back (MLP=8).
    #pragma unroll 2
    for (int k = 0; k < D_DIM / (32 * 4); ++k) {
        const int idx = (k * 32 + lane) * 4;

        float4 t[EDGES_PER_WARP];
        #pragma unroll
        for (int e = 0; e < EDGES_PER_WARP; ++e)
            t[e] = __ldg(reinterpret_cast<const float4*>(
                       xr + (size_t)dI[e] * D_DIM + idx));

        const float4 r = __ldg(reinterpret_cast<const float4*>(rel + idx));

        float4 hr;   // head chunk pre-multiplied by rel; reload on key change
        #pragma unroll
        for (int e = 0; e < EDGES_PER_WARP; ++e) {
            if (e == 0 || s[e] != s[e - 1]) {   // warp-uniform branch
                float4 h = __ldg(reinterpret_cast<const float4*>(
                               xs + (size_t)s[e] * D_DIM + idx));
                hr.x = h.x * r.x; hr.y = h.y * r.y;
                hr.z = h.z * r.z; hr.w = h.w * r.w;
            }
            acc[e] = fmaf(hr.x, t[e].x, acc[e]);
            acc[e] = fmaf(hr.y, t[e].y, acc[e]);
            acc[e] = fmaf(hr.z, t[e].z, acc[e]);
            acc[e] = fmaf(hr.w, t[e].w, acc[e]);
        }
    }

    // Reduce and write each edge's score.
    #pragma unroll
    for (int e = 0; e < EDGES_PER_WARP; ++e) {
        float a = acc[e];
        #pragma unroll
        for (int off = 16; off > 0; off >>= 1)
            a += __shfl_xor_sync(0xffffffffu, a, off);
        const int edge_e = __shfl_sync(0xffffffffu, my_edge, e);
        if (lane == 0)
            o[edge_e] = fminf(fmaxf(a, 0.0f), 1.0f);
    }
}

// ---------------- launch ----------------

extern "C" void kernel_launch(void* const* d_in, const int* in_sizes, int n_in,
                              void* d_out, int out_size)
{
    const float* x_drug  = (const float*)d_in[0];
    const float* x_prot  = (const float*)d_in[1];
    const float* rel_ddi = (const float*)d_in[2];
    const float* rel_dpi = (const float*)d_in[3];
    const int*   ddi_src = (const int*)d_in[4];
    const int*   ddi_dst = (const int*)d_in[5];
    const int*   dpi_src = (const int*)d_in[6];
    const int*   dpi_dst = (const int*)d_in[7];
    const int*   ppi_src = (const int*)d_in[8];
    const int*   ppi_dst = (const int*)d_in[9];
    float* out = (float*)d_out;

    const int E      = in_sizes[4];
    const int N_DRUG = in_sizes[0] / D_DIM;
    const int N_PROT = in_sizes[1] / D_DIM;

    // Sort each edge list by its grouping endpoint (ddi:src, dpi:dst, ppi:src).
    zero_hist_kernel<<<(3 * MAX_BINS + 255) / 256, 256>>>();
    hist_kernel<<<(3 * E + 255) / 256, 256>>>(ddi_src, dpi_dst, ppi_src, E);
    scan_kernel<<<3, 1024>>>(N_DRUG, N_PROT);
    scatter_kernel<<<(3 * E + 255) / 256, 256>>>(ddi_src, dpi_dst, ppi_src, E);

    const int bpp = (E + EDGES_PER_BLOCK - 1) / EDGES_PER_BLOCK;

    edge_score_fused<<<3 * bpp, THREADS_PER_BLOCK>>>(
        x_drug, x_prot, rel_ddi, rel_dpi,
        ddi_src, ddi_dst, dpi_src, dpi_dst, ppi_src, ppi_dst,
        out, E, bpp);
}